// round 3
// baseline (speedup 1.0000x reference)
#include <cuda_runtime.h>
#include <math.h>

#define VSZ 32000
#define ESZ 400
#define HSZ 1150
#define HPAD 1152
#define BSZ 16
#define TSZ 128
#define GP12 4608   // padded gate-row count for layers 1/2 (144 blocks * 32)
#define GP3  1600   // layer 3 gate rows (50 blocks * 32, exact)

// ---------------- scratch (device globals; no allocation allowed) ----------------
__device__ float g_y0[TSZ*BSZ*ESZ];
__device__ float g_y1[TSZ*BSZ*HPAD];
__device__ float g_y2[TSZ*BSZ*HPAD];
__device__ float g_y3[TSZ*BSZ*ESZ];
__device__ float g_pre[TSZ*BSZ*4*HSZ];
__device__ float g_Wt1[HSZ*GP12];
__device__ float g_Wt2[HSZ*GP12];
__device__ float g_Wt3[ESZ*GP3];
__device__ float g_Wih2p[4*HSZ*HPAD];
__device__ float g_Wih3p[4*ESZ*HPAD];
__device__ float g_hTa[HSZ*BSZ];
__device__ float g_hTb[HSZ*BSZ];
__device__ float g_cT1[HSZ*BSZ];
__device__ float g_cT2[HSZ*BSZ];
__device__ float g_cT3[ESZ*BSZ];

// ---------------- tiny utility kernels ----------------
__global__ void zero_k(float* __restrict__ p, int n) {
    int i = blockIdx.x * blockDim.x + threadIdx.x;
    if (i < n) p[i] = 0.f;
}

__global__ void pad_k(const float* __restrict__ src, float* __restrict__ dst,
                      int rows, int Kin, int Kout) {
    int idx = blockIdx.x * blockDim.x + threadIdx.x;
    if (idx >= rows * Kout) return;
    int r = idx / Kout, k = idx % Kout;
    dst[idx] = (k < Kin) ? src[(size_t)r * Kin + k] : 0.f;
}

// y0[(b*T+t)*E + e] = emb[x[b*T+t]*E + e]
__global__ void embed_k(const float* __restrict__ emb, const int* __restrict__ x,
                        float* __restrict__ y0) {
    int idx = blockIdx.x * blockDim.x + threadIdx.x;
    if (idx >= TSZ * BSZ * ESZ) return;
    int e   = idx % ESZ;
    int row = idx / ESZ;      // b*T + t
    y0[idx] = emb[(size_t)x[row] * ESZ + e];
}

// Gate-permuted transpose of W_hh
__global__ void wtrans_k(const float* __restrict__ W, float* __restrict__ Wt,
                         int Hp, int Gp) {
    __shared__ float tile[32][33];
    int jblk = blockIdx.x;
    int k0   = blockIdx.y * 32;
    for (int rr = 0; rr < 32; rr += 8) {
        int r = rr + threadIdx.y;
        int g = r >> 3, u = r & 7;
        int j = jblk * 8 + u;
        int orow = g * Hp + j;
        int k = k0 + threadIdx.x;
        tile[r][threadIdx.x] = (j < Hp && k < Hp) ? W[(size_t)orow * Hp + k] : 0.f;
    }
    __syncthreads();
    for (int kk = 0; kk < 32; kk += 8) {
        int k = k0 + kk + threadIdx.y;
        if (k < Hp)
            Wt[(size_t)k * Gp + jblk * 32 + threadIdx.x] = tile[threadIdx.x][kk + threadIdx.y];
    }
}

// ---------------- tf32x2 tensor-core GEMM:  C = A(MxK) * B(NxK)^T + bias ----------------
__device__ __forceinline__ float tf32_rna(float x) {
    float r;
    asm("cvt.rna.tf32.f32 %0, %1;" : "=f"(r) : "f"(x));
    return r;
}

__device__ __forceinline__ void mma_tf32(float4& d, const float* a, const float* b) {
    asm volatile(
        "mma.sync.aligned.m16n8k8.row.col.f32.tf32.tf32.f32 "
        "{%0,%1,%2,%3}, {%4,%5,%6,%7}, {%8,%9}, {%0,%1,%2,%3};\n"
        : "+f"(d.x), "+f"(d.y), "+f"(d.z), "+f"(d.w)
        : "r"(__float_as_uint(a[0])), "r"(__float_as_uint(a[1])),
          "r"(__float_as_uint(a[2])), "r"(__float_as_uint(a[3])),
          "r"(__float_as_uint(b[0])), "r"(__float_as_uint(b[1])));
}

#define SSTR 20   // smem row stride (bank-conflict-free for quad-pattern frag loads)

// BM=BN=128, BK=16, 256 threads (8 warps), warp tile 64x32 (4x4 m16n8 tiles).
// Requirements: M % 128 == 0, K % 16 == 0.
// mode 0: C[m*N + n];  mode 1: C[((b*N + n)*T) + t], m = b*T + t.
__global__ __launch_bounds__(256)
void gemm_tc(const float* __restrict__ A, const float* __restrict__ Bm,
             const float* __restrict__ bias1, const float* __restrict__ bias2,
             float* __restrict__ C, int M, int N, int K, int mode) {
    __shared__ float As[2][128 * SSTR];   // [hi/lo][m*SSTR + k]
    __shared__ float Bs[2][128 * SSTR];   // [hi/lo][n*SSTR + k]

    const int tid  = threadIdx.x;
    const int lane = tid & 31;
    const int w    = tid >> 5;
    const int wm   = (w & 1) * 64;
    const int wn   = (w >> 1) * 32;
    const int qr   = lane >> 2;   // 0..7
    const int qc   = lane & 3;    // 0..3

    const int m0 = blockIdx.y * 128;
    const int n0 = blockIdx.x * 128;

    const int lrow = tid >> 1;        // 0..127
    const int lk   = (tid & 1) * 8;   // 0 or 8

    const float* Aptr = A + (size_t)(m0 + lrow) * K + lk;
    const float* Bptr = Bm + (size_t)(n0 + lrow) * K + lk;
    const bool bvalid = (n0 + lrow) < N;

    float4 acc[4][4];
#pragma unroll
    for (int i = 0; i < 4; i++)
#pragma unroll
        for (int j = 0; j < 4; j++) acc[i][j] = make_float4(0.f, 0.f, 0.f, 0.f);

    for (int k0 = 0; k0 < K; k0 += 16) {
        // load 128x16 A and B slabs, split into tf32 hi/lo
        float4 av0 = *(const float4*)(Aptr + k0);
        float4 av1 = *(const float4*)(Aptr + k0 + 4);
        float4 bv0 = bvalid ? *(const float4*)(Bptr + k0) : make_float4(0.f, 0.f, 0.f, 0.f);
        float4 bv1 = bvalid ? *(const float4*)(Bptr + k0 + 4) : make_float4(0.f, 0.f, 0.f, 0.f);
        __syncthreads();   // protect previous iteration's reads
        {
            float va[8] = {av0.x, av0.y, av0.z, av0.w, av1.x, av1.y, av1.z, av1.w};
            float vb[8] = {bv0.x, bv0.y, bv0.z, bv0.w, bv1.x, bv1.y, bv1.z, bv1.w};
            int base = lrow * SSTR + lk;
#pragma unroll
            for (int j = 0; j < 8; j++) {
                float hi = tf32_rna(va[j]);
                As[0][base + j] = hi;
                As[1][base + j] = tf32_rna(va[j] - hi);
                float bhi = tf32_rna(vb[j]);
                Bs[0][base + j] = bhi;
                Bs[1][base + j] = tf32_rna(vb[j] - bhi);
            }
        }
        __syncthreads();

#pragma unroll
        for (int kk = 0; kk < 16; kk += 8) {
            float ah[4][4], al[4][4], bh[4][2], bl[4][2];
#pragma unroll
            for (int mt = 0; mt < 4; mt++) {
                int base = (wm + mt * 16 + qr) * SSTR + kk + qc;
                ah[mt][0] = As[0][base];
                ah[mt][1] = As[0][base + 8 * SSTR];
                ah[mt][2] = As[0][base + 4];
                ah[mt][3] = As[0][base + 8 * SSTR + 4];
                al[mt][0] = As[1][base];
                al[mt][1] = As[1][base + 8 * SSTR];
                al[mt][2] = As[1][base + 4];
                al[mt][3] = As[1][base + 8 * SSTR + 4];
            }
#pragma unroll
            for (int nt = 0; nt < 4; nt++) {
                int base = (wn + nt * 8 + qr) * SSTR + kk + qc;
                bh[nt][0] = Bs[0][base];
                bh[nt][1] = Bs[0][base + 4];
                bl[nt][0] = Bs[1][base];
                bl[nt][1] = Bs[1][base + 4];
            }
#pragma unroll
            for (int mt = 0; mt < 4; mt++)
#pragma unroll
                for (int nt = 0; nt < 4; nt++) {
                    mma_tf32(acc[mt][nt], ah[mt], bh[nt]);
                    mma_tf32(acc[mt][nt], ah[mt], bl[nt]);
                    mma_tf32(acc[mt][nt], al[mt], bh[nt]);
                }
        }
    }

    // epilogue
#pragma unroll
    for (int mt = 0; mt < 4; mt++) {
        int mrow = m0 + wm + mt * 16 + qr;
#pragma unroll
        for (int nt = 0; nt < 4; nt++) {
            int n = n0 + wn + nt * 8 + 2 * qc;
            if (n >= N) continue;
            float b0 = 0.f, b1 = 0.f;
            if (bias1) { b0 += bias1[n]; b1 += bias1[n + 1]; }
            if (bias2) { b0 += bias2[n]; b1 += bias2[n + 1]; }
            float4 v = acc[mt][nt];
            if (mode == 0) {
                C[(size_t)mrow * N + n]           = v.x + b0;
                C[(size_t)mrow * N + n + 1]       = v.y + b1;
                C[(size_t)(mrow + 8) * N + n]     = v.z + b0;
                C[(size_t)(mrow + 8) * N + n + 1] = v.w + b1;
            } else {
                int bidx = m0 >> 7;
                int t = (mrow - m0);   // wm + mt*16 + qr
                size_t base = ((size_t)bidx * N + n) * TSZ + t;
                C[base]           = v.x + b0;
                C[base + TSZ]     = v.y + b1;
                C[base + 8]       = v.z + b0;
                C[base + TSZ + 8] = v.w + b1;
            }
        }
    }
}

// ---------------- fused LSTM step ----------------
__device__ __forceinline__ float sigf(float z) { return 1.f / (1.f + expf(-z)); }

__global__ __launch_bounds__(256)
void lstm_step_k(const float* __restrict__ pre, const float* __restrict__ Wt,
                 const float* __restrict__ hin, float* __restrict__ hout,
                 float* __restrict__ cT, float* __restrict__ y,
                 int Hp, int Gp, int ldy, int t) {
    int r = threadIdx.x & 31;
    int s = threadIdx.x >> 5;
    int col = blockIdx.x * 32 + r;

    float acc[16];
#pragma unroll
    for (int i = 0; i < 16; i++) acc[i] = 0.f;

    const float4* hv4 = (const float4*)hin;
#pragma unroll 4
    for (int k = s; k < Hp; k += 8) {
        float w = Wt[(size_t)k * Gp + col];
        float4 h0 = hv4[k * 4 + 0];
        float4 h1 = hv4[k * 4 + 1];
        float4 h2 = hv4[k * 4 + 2];
        float4 h3 = hv4[k * 4 + 3];
        acc[0]  += w * h0.x; acc[1]  += w * h0.y; acc[2]  += w * h0.z; acc[3]  += w * h0.w;
        acc[4]  += w * h1.x; acc[5]  += w * h1.y; acc[6]  += w * h1.z; acc[7]  += w * h1.w;
        acc[8]  += w * h2.x; acc[9]  += w * h2.y; acc[10] += w * h2.z; acc[11] += w * h2.w;
        acc[12] += w * h3.x; acc[13] += w * h3.y; acc[14] += w * h3.z; acc[15] += w * h3.w;
    }

    __shared__ float red[8][32][16];
    float4* rp = (float4*)&red[s][r][0];
    rp[0] = make_float4(acc[0], acc[1], acc[2], acc[3]);
    rp[1] = make_float4(acc[4], acc[5], acc[6], acc[7]);
    rp[2] = make_float4(acc[8], acc[9], acc[10], acc[11]);
    rp[3] = make_float4(acc[12], acc[13], acc[14], acc[15]);
    __syncthreads();

    if (threadIdx.x < 128) {
        int u = threadIdx.x >> 4;
        int b = threadIdx.x & 15;
        int j = blockIdx.x * 8 + u;
        if (j < Hp) {
            int G = 4 * Hp;
            size_t row = (size_t)b * TSZ + t;
            const float* prow = pre + row * G + j;
            float gv[4];
#pragma unroll
            for (int g = 0; g < 4; g++) {
                float sum = prow[(size_t)g * Hp];
#pragma unroll
                for (int s2 = 0; s2 < 8; s2++) sum += red[s2][g * 8 + u][b];
                gv[g] = sum;
            }
            float ig = sigf(gv[0]);
            float fg = sigf(gv[1]);
            float gg = tanhf(gv[2]);
            float og = sigf(gv[3]);
            float c  = fg * cT[j * 16 + b] + ig * gg;
            float hn = og * tanhf(c);
            cT[j * 16 + b]   = c;
            hout[j * 16 + b] = hn;
            y[row * ldy + j] = hn;
        }
    }
}

// ---------------- finalize ----------------
__global__ void finalize_k(const float* __restrict__ y1, const float* __restrict__ y2,
                           const float* __restrict__ y3, const float* __restrict__ cT1,
                           const float* __restrict__ cT2, const float* __restrict__ cT3,
                           float* __restrict__ out) {
    int i = blockIdx.x * blockDim.x + threadIdx.x;
    if (i >= 86400) return;
    const size_t O = (size_t)BSZ * VSZ * TSZ;
    if (i < 18400) {
        int b = i / 1150, j = i % 1150;
        out[O + i] = y1[((size_t)b * TSZ + 127) * HPAD + j];
    } else if (i < 36800) {
        int k = i - 18400; int b = k / 1150, j = k % 1150;
        out[O + i] = y2[((size_t)b * TSZ + 127) * HPAD + j];
    } else if (i < 43200) {
        int k = i - 36800; int b = k / 400, j = k % 400;
        out[O + i] = y3[((size_t)b * TSZ + 127) * 400 + j];
    } else if (i < 61600) {
        int k = i - 43200; int j = (k % 1150), b = k / 1150;
        out[O + i] = cT1[j * 16 + b];
    } else if (i < 80000) {
        int k = i - 61600; int j = (k % 1150), b = k / 1150;
        out[O + i] = cT2[j * 16 + b];
    } else {
        int k = i - 80000; int j = (k % 400), b = k / 400;
        out[O + i] = cT3[j * 16 + b];
    }
}

// ---------------- launch ----------------
extern "C" void kernel_launch(void* const* d_in, const int* in_sizes, int n_in,
                              void* d_out, int out_size) {
    const float* emb  = (const float*)d_in[0];
    const float* Wih1 = (const float*)d_in[1];
    const float* Whh1 = (const float*)d_in[2];
    const float* bih1 = (const float*)d_in[3];
    const float* bhh1 = (const float*)d_in[4];
    const float* Wih2 = (const float*)d_in[5];
    const float* Whh2 = (const float*)d_in[6];
    const float* bih2 = (const float*)d_in[7];
    const float* bhh2 = (const float*)d_in[8];
    const float* Wih3 = (const float*)d_in[9];
    const float* Whh3 = (const float*)d_in[10];
    const float* bih3 = (const float*)d_in[11];
    const float* bhh3 = (const float*)d_in[12];
    const float* linb = (const float*)d_in[13];
    const int*   x    = (const int*)d_in[14];
    float* out = (float*)d_out;

    float *y0, *y1, *y2, *y3, *pre, *Wt1, *Wt2, *Wt3, *W2p, *W3p;
    float *hTa, *hTb, *cT1, *cT2, *cT3;
    cudaGetSymbolAddress((void**)&y0,  g_y0);
    cudaGetSymbolAddress((void**)&y1,  g_y1);
    cudaGetSymbolAddress((void**)&y2,  g_y2);
    cudaGetSymbolAddress((void**)&y3,  g_y3);
    cudaGetSymbolAddress((void**)&pre, g_pre);
    cudaGetSymbolAddress((void**)&Wt1, g_Wt1);
    cudaGetSymbolAddress((void**)&Wt2, g_Wt2);
    cudaGetSymbolAddress((void**)&Wt3, g_Wt3);
    cudaGetSymbolAddress((void**)&W2p, g_Wih2p);
    cudaGetSymbolAddress((void**)&W3p, g_Wih3p);
    cudaGetSymbolAddress((void**)&hTa, g_hTa);
    cudaGetSymbolAddress((void**)&hTb, g_hTb);
    cudaGetSymbolAddress((void**)&cT1, g_cT1);
    cudaGetSymbolAddress((void**)&cT2, g_cT2);
    cudaGetSymbolAddress((void**)&cT3, g_cT3);

    const int M = TSZ * BSZ;  // 2048

    // setup — layer-1 GEMM placed as 4th launch for ncu visibility
    embed_k<<<(TSZ * BSZ * ESZ + 255) / 256, 256>>>(emb, x, y0);
    wtrans_k<<<dim3(GP12 / 32, (HSZ + 31) / 32), dim3(32, 8)>>>(Whh1, Wt1, HSZ, GP12);
    wtrans_k<<<dim3(GP12 / 32, (HSZ + 31) / 32), dim3(32, 8)>>>(Whh2, Wt2, HSZ, GP12);
    gemm_tc<<<dim3((4 * HSZ + 127) / 128, M / 128), 256>>>(y0, Wih1, bih1, bhh1, pre,
                                                           M, 4 * HSZ, ESZ, 0);
    wtrans_k<<<dim3(GP3 / 32, (ESZ + 31) / 32), dim3(32, 8)>>>(Whh3, Wt3, ESZ, GP3);
    pad_k<<<(4 * HSZ * HPAD + 255) / 256, 256>>>(Wih2, W2p, 4 * HSZ, HSZ, HPAD);
    pad_k<<<(4 * ESZ * HPAD + 255) / 256, 256>>>(Wih3, W3p, 4 * ESZ, HSZ, HPAD);
    zero_k<<<(M * HPAD + 255) / 256, 256>>>(y1, M * HPAD);
    zero_k<<<(M * HPAD + 255) / 256, 256>>>(y2, M * HPAD);
    zero_k<<<(HSZ * BSZ + 255) / 256, 256>>>(cT1, HSZ * BSZ);
    zero_k<<<(HSZ * BSZ + 255) / 256, 256>>>(cT2, HSZ * BSZ);
    zero_k<<<(ESZ * BSZ + 255) / 256, 256>>>(cT3, ESZ * BSZ);

    // ----- layer 1 recurrence -----
    zero_k<<<(HSZ * BSZ + 255) / 256, 256>>>(hTa, HSZ * BSZ);
    for (int t = 0; t < TSZ; t++) {
        float* hin  = (t & 1) ? hTb : hTa;
        float* hout = (t & 1) ? hTa : hTb;
        lstm_step_k<<<GP12 / 32, 256>>>(pre, Wt1, hin, hout, cT1, y1, HSZ, GP12, HPAD, t);
    }

    // ----- layer 2 -----
    gemm_tc<<<dim3((4 * HSZ + 127) / 128, M / 128), 256>>>(y1, W2p, bih2, bhh2, pre,
                                                           M, 4 * HSZ, HPAD, 0);
    zero_k<<<(HSZ * BSZ + 255) / 256, 256>>>(hTa, HSZ * BSZ);
    for (int t = 0; t < TSZ; t++) {
        float* hin  = (t & 1) ? hTb : hTa;
        float* hout = (t & 1) ? hTa : hTb;
        lstm_step_k<<<GP12 / 32, 256>>>(pre, Wt2, hin, hout, cT2, y2, HSZ, GP12, HPAD, t);
    }

    // ----- layer 3 -----
    gemm_tc<<<dim3((4 * ESZ + 127) / 128, M / 128), 256>>>(y2, W3p, bih3, bhh3, pre,
                                                           M, 4 * ESZ, HPAD, 0);
    zero_k<<<(ESZ * BSZ + 255) / 256, 256>>>(hTa, ESZ * BSZ);
    for (int t = 0; t < TSZ; t++) {
        float* hin  = (t & 1) ? hTb : hTa;
        float* hout = (t & 1) ? hTa : hTb;
        lstm_step_k<<<GP3 / 32, 256>>>(pre, Wt3, hin, hout, cT3, y3, ESZ, GP3, ESZ, t);
    }

    // ----- tied output projection into (B,V,T) -----
    gemm_tc<<<dim3(VSZ / 128, M / 128), 256>>>(y3, emb, linb, nullptr, out,
                                               M, VSZ, ESZ, 1);

    // ----- final states -----
    finalize_k<<<(86400 + 255) / 256, 256>>>(y1, y2, y3, cT1, cT2, cT3, out);
}

// round 4
// speedup vs baseline: 2.2347x; 2.2347x over previous
#include <cuda_runtime.h>
#include <math.h>

#define VSZ 32000
#define ESZ 400
#define HSZ 1150
#define HPAD 1152
#define BSZ 16
#define TSZ 128
#define GP12 4608   // padded gate-col count for layers 1/2 (144 CTAs * 32)
#define GP3  1600   // layer 3 gate cols (50 CTAs * 32)

// ---------------- scratch (device globals; no allocation allowed) ----------------
__device__ float g_y0[TSZ*BSZ*ESZ];
__device__ float g_y1[TSZ*BSZ*HPAD];
__device__ float g_y2[TSZ*BSZ*HPAD];
__device__ float g_y3[TSZ*BSZ*ESZ];
__device__ float g_pre[TSZ*BSZ*4*HSZ];
__device__ float g_Wt1[HSZ*GP12];
__device__ float g_Wt2[HSZ*GP12];
__device__ float g_Wt3[ESZ*GP3];
__device__ float g_Wih2p[4*HSZ*HPAD];
__device__ float g_Wih3p[4*ESZ*HPAD];
__device__ float g_hTa[HSZ*BSZ];
__device__ float g_hTb[HSZ*BSZ];
__device__ float g_cT1[HSZ*BSZ];
__device__ float g_cT2[HSZ*BSZ];
__device__ float g_cT3[ESZ*BSZ];
__device__ unsigned g_bar[4];

// ---------------- tiny utility kernels ----------------
__global__ void zero_k(float* __restrict__ p, int n) {
    int i = blockIdx.x * blockDim.x + threadIdx.x;
    if (i < n) p[i] = 0.f;
}

__global__ void pad_k(const float* __restrict__ src, float* __restrict__ dst,
                      int rows, int Kin, int Kout) {
    int idx = blockIdx.x * blockDim.x + threadIdx.x;
    if (idx >= rows * Kout) return;
    int r = idx / Kout, k = idx % Kout;
    dst[idx] = (k < Kin) ? src[(size_t)r * Kin + k] : 0.f;
}

__global__ void embed_k(const float* __restrict__ emb, const int* __restrict__ x,
                        float* __restrict__ y0) {
    int idx = blockIdx.x * blockDim.x + threadIdx.x;
    if (idx >= TSZ * BSZ * ESZ) return;
    int e   = idx % ESZ;
    int row = idx / ESZ;      // b*T + t
    y0[idx] = emb[(size_t)x[row] * ESZ + e];
}

// Gate-permuted transpose of W_hh
__global__ void wtrans_k(const float* __restrict__ W, float* __restrict__ Wt,
                         int Hp, int Gp) {
    __shared__ float tile[32][33];
    int jblk = blockIdx.x;
    int k0   = blockIdx.y * 32;
    for (int rr = 0; rr < 32; rr += 8) {
        int r = rr + threadIdx.y;
        int g = r >> 3, u = r & 7;
        int j = jblk * 8 + u;
        int orow = g * Hp + j;
        int k = k0 + threadIdx.x;
        tile[r][threadIdx.x] = (j < Hp && k < Hp) ? W[(size_t)orow * Hp + k] : 0.f;
    }
    __syncthreads();
    for (int kk = 0; kk < 32; kk += 8) {
        int k = k0 + kk + threadIdx.y;
        if (k < Hp)
            Wt[(size_t)k * Gp + jblk * 32 + threadIdx.x] = tile[threadIdx.x][kk + threadIdx.y];
    }
}

// ---------------- tf32x2 tensor-core GEMM (unchanged from R3) ----------------
__device__ __forceinline__ float tf32_rna(float x) {
    float r;
    asm("cvt.rna.tf32.f32 %0, %1;" : "=f"(r) : "f"(x));
    return r;
}

__device__ __forceinline__ void mma_tf32(float4& d, const float* a, const float* b) {
    asm volatile(
        "mma.sync.aligned.m16n8k8.row.col.f32.tf32.tf32.f32 "
        "{%0,%1,%2,%3}, {%4,%5,%6,%7}, {%8,%9}, {%0,%1,%2,%3};\n"
        : "+f"(d.x), "+f"(d.y), "+f"(d.z), "+f"(d.w)
        : "r"(__float_as_uint(a[0])), "r"(__float_as_uint(a[1])),
          "r"(__float_as_uint(a[2])), "r"(__float_as_uint(a[3])),
          "r"(__float_as_uint(b[0])), "r"(__float_as_uint(b[1])));
}

#define SSTR 20

__global__ __launch_bounds__(256)
void gemm_tc(const float* __restrict__ A, const float* __restrict__ Bm,
             const float* __restrict__ bias1, const float* __restrict__ bias2,
             float* __restrict__ C, int M, int N, int K, int mode) {
    __shared__ float As[2][128 * SSTR];
    __shared__ float Bs[2][128 * SSTR];

    const int tid  = threadIdx.x;
    const int lane = tid & 31;
    const int w    = tid >> 5;
    const int wm   = (w & 1) * 64;
    const int wn   = (w >> 1) * 32;
    const int qr   = lane >> 2;
    const int qc   = lane & 3;

    const int m0 = blockIdx.y * 128;
    const int n0 = blockIdx.x * 128;

    const int lrow = tid >> 1;
    const int lk   = (tid & 1) * 8;

    const float* Aptr = A + (size_t)(m0 + lrow) * K + lk;
    const float* Bptr = Bm + (size_t)(n0 + lrow) * K + lk;
    const bool bvalid = (n0 + lrow) < N;

    float4 acc[4][4];
#pragma unroll
    for (int i = 0; i < 4; i++)
#pragma unroll
        for (int j = 0; j < 4; j++) acc[i][j] = make_float4(0.f, 0.f, 0.f, 0.f);

    for (int k0 = 0; k0 < K; k0 += 16) {
        float4 av0 = *(const float4*)(Aptr + k0);
        float4 av1 = *(const float4*)(Aptr + k0 + 4);
        float4 bv0 = bvalid ? *(const float4*)(Bptr + k0) : make_float4(0.f, 0.f, 0.f, 0.f);
        float4 bv1 = bvalid ? *(const float4*)(Bptr + k0 + 4) : make_float4(0.f, 0.f, 0.f, 0.f);
        __syncthreads();
        {
            float va[8] = {av0.x, av0.y, av0.z, av0.w, av1.x, av1.y, av1.z, av1.w};
            float vb[8] = {bv0.x, bv0.y, bv0.z, bv0.w, bv1.x, bv1.y, bv1.z, bv1.w};
            int base = lrow * SSTR + lk;
#pragma unroll
            for (int j = 0; j < 8; j++) {
                float hi = tf32_rna(va[j]);
                As[0][base + j] = hi;
                As[1][base + j] = tf32_rna(va[j] - hi);
                float bhi = tf32_rna(vb[j]);
                Bs[0][base + j] = bhi;
                Bs[1][base + j] = tf32_rna(vb[j] - bhi);
            }
        }
        __syncthreads();

#pragma unroll
        for (int kk = 0; kk < 16; kk += 8) {
            float ah[4][4], al[4][4], bh[4][2], bl[4][2];
#pragma unroll
            for (int mt = 0; mt < 4; mt++) {
                int base = (wm + mt * 16 + qr) * SSTR + kk + qc;
                ah[mt][0] = As[0][base];
                ah[mt][1] = As[0][base + 8 * SSTR];
                ah[mt][2] = As[0][base + 4];
                ah[mt][3] = As[0][base + 8 * SSTR + 4];
                al[mt][0] = As[1][base];
                al[mt][1] = As[1][base + 8 * SSTR];
                al[mt][2] = As[1][base + 4];
                al[mt][3] = As[1][base + 8 * SSTR + 4];
            }
#pragma unroll
            for (int nt = 0; nt < 4; nt++) {
                int base = (wn + nt * 8 + qr) * SSTR + kk + qc;
                bh[nt][0] = Bs[0][base];
                bh[nt][1] = Bs[0][base + 4];
                bl[nt][0] = Bs[1][base];
                bl[nt][1] = Bs[1][base + 4];
            }
#pragma unroll
            for (int mt = 0; mt < 4; mt++)
#pragma unroll
                for (int nt = 0; nt < 4; nt++) {
                    mma_tf32(acc[mt][nt], ah[mt], bh[nt]);
                    mma_tf32(acc[mt][nt], ah[mt], bl[nt]);
                    mma_tf32(acc[mt][nt], al[mt], bh[nt]);
                }
        }
    }

#pragma unroll
    for (int mt = 0; mt < 4; mt++) {
        int mrow = m0 + wm + mt * 16 + qr;
#pragma unroll
        for (int nt = 0; nt < 4; nt++) {
            int n = n0 + wn + nt * 8 + 2 * qc;
            if (n >= N) continue;
            float b0 = 0.f, b1 = 0.f;
            if (bias1) { b0 += bias1[n]; b1 += bias1[n + 1]; }
            if (bias2) { b0 += bias2[n]; b1 += bias2[n + 1]; }
            float4 v = acc[mt][nt];
            if (mode == 0) {
                C[(size_t)mrow * N + n]           = v.x + b0;
                C[(size_t)mrow * N + n + 1]       = v.y + b1;
                C[(size_t)(mrow + 8) * N + n]     = v.z + b0;
                C[(size_t)(mrow + 8) * N + n + 1] = v.w + b1;
            } else {
                int bidx = m0 >> 7;
                int t = (mrow - m0);
                size_t base = ((size_t)bidx * N + n) * TSZ + t;
                C[base]           = v.x + b0;
                C[base + TSZ]     = v.y + b1;
                C[base + 8]       = v.z + b0;
                C[base + TSZ + 8] = v.w + b1;
            }
        }
    }
}

// ---------------- persistent LSTM layer kernel ----------------
// grid = Gp/32 CTAs, all co-resident (1 CTA/SM via smem). Each CTA stages its
// 32 weight columns into smem once, then loops all T steps with a software
// grid barrier between steps.
__device__ __forceinline__ float sigf(float z) { return 1.f / (1.f + expf(-z)); }

__device__ __forceinline__ void grid_bar(unsigned* bar, unsigned target) {
    __syncthreads();
    if (threadIdx.x == 0) {
        __threadfence();
        atomicAdd(bar, 1u);
        while (*(volatile unsigned*)bar < target) {}
        __threadfence();
    }
    __syncthreads();
}

__global__ __launch_bounds__(256, 1)
void lstm_layer_k(const float* __restrict__ pre, const float* __restrict__ Wt,
                  float* __restrict__ hA, float* __restrict__ hB,
                  float* __restrict__ cOut, float* __restrict__ y,
                  int Hp, int Gp, int ldy, unsigned* bar) {
    extern __shared__ float sm[];
    float* sW  = sm;                 // Hp*32
    float* red = sm + Hp * 32;       // 8*32*16 = 4096
    float* cT  = red + 4096;         // 128

    const int tid  = threadIdx.x;
    const int jblk = blockIdx.x;
    const int nCTA = gridDim.x;
    const int r = tid & 31;
    const int s = tid >> 5;
    const int G4 = 4 * Hp;

    // stage weights into smem (coalesced)
    for (int idx = tid; idx < Hp * 32; idx += 256) {
        int k = idx >> 5, rr = idx & 31;
        sW[idx] = Wt[(size_t)k * Gp + jblk * 32 + rr];
    }
    // zero owned h(t=0) entries and local c
    if (tid < 128) {
        int u = tid >> 4, b = tid & 15;
        int j = jblk * 8 + u;
        cT[tid] = 0.f;
        if (j < Hp) hA[j * 16 + b] = 0.f;
    }
    grid_bar(bar, (unsigned)nCTA);

    for (int t = 0; t < TSZ; t++) {
        const float* hin = (t & 1) ? hB : hA;
        float* hout      = (t & 1) ? hA : hB;

        float acc[16];
#pragma unroll
        for (int i = 0; i < 16; i++) acc[i] = 0.f;

        const float4* hv4 = (const float4*)hin;
#pragma unroll 4
        for (int k = s; k < Hp; k += 8) {
            float w = sW[(k << 5) + r];
            float4 h0 = hv4[k * 4 + 0];
            float4 h1 = hv4[k * 4 + 1];
            float4 h2 = hv4[k * 4 + 2];
            float4 h3 = hv4[k * 4 + 3];
            acc[0]  += w * h0.x; acc[1]  += w * h0.y; acc[2]  += w * h0.z; acc[3]  += w * h0.w;
            acc[4]  += w * h1.x; acc[5]  += w * h1.y; acc[6]  += w * h1.z; acc[7]  += w * h1.w;
            acc[8]  += w * h2.x; acc[9]  += w * h2.y; acc[10] += w * h2.z; acc[11] += w * h2.w;
            acc[12] += w * h3.x; acc[13] += w * h3.y; acc[14] += w * h3.z; acc[15] += w * h3.w;
        }

        float4* rp = (float4*)&red[(s * 32 + r) * 16];
        rp[0] = make_float4(acc[0], acc[1], acc[2], acc[3]);
        rp[1] = make_float4(acc[4], acc[5], acc[6], acc[7]);
        rp[2] = make_float4(acc[8], acc[9], acc[10], acc[11]);
        rp[3] = make_float4(acc[12], acc[13], acc[14], acc[15]);
        __syncthreads();

        if (tid < 128) {
            int u = tid >> 4;
            int b = tid & 15;
            int j = jblk * 8 + u;
            if (j < Hp) {
                size_t row = (size_t)b * TSZ + t;
                const float* prow = pre + row * G4 + j;
                float gv[4];
#pragma unroll
                for (int g = 0; g < 4; g++) {
                    float sum = prow[(size_t)g * Hp];
#pragma unroll
                    for (int s2 = 0; s2 < 8; s2++)
                        sum += red[(s2 * 32 + g * 8 + u) * 16 + b];
                    gv[g] = sum;
                }
                float ig = sigf(gv[0]);
                float fg = sigf(gv[1]);
                float gg = tanhf(gv[2]);
                float og = sigf(gv[3]);
                float c  = fg * cT[tid] + ig * gg;
                float hn = og * tanhf(c);
                cT[tid] = c;
                hout[j * 16 + b] = hn;
                y[row * ldy + j] = hn;
                if (t == TSZ - 1) cOut[j * 16 + b] = c;
            }
        }
        grid_bar(bar, (unsigned)(nCTA * (t + 2)));
    }
}

// ---------------- finalize ----------------
__global__ void finalize_k(const float* __restrict__ y1, const float* __restrict__ y2,
                           const float* __restrict__ y3, const float* __restrict__ cT1,
                           const float* __restrict__ cT2, const float* __restrict__ cT3,
                           float* __restrict__ out) {
    int i = blockIdx.x * blockDim.x + threadIdx.x;
    if (i >= 86400) return;
    const size_t O = (size_t)BSZ * VSZ * TSZ;
    if (i < 18400) {
        int b = i / 1150, j = i % 1150;
        out[O + i] = y1[((size_t)b * TSZ + 127) * HPAD + j];
    } else if (i < 36800) {
        int k = i - 18400; int b = k / 1150, j = k % 1150;
        out[O + i] = y2[((size_t)b * TSZ + 127) * HPAD + j];
    } else if (i < 43200) {
        int k = i - 36800; int b = k / 400, j = k % 400;
        out[O + i] = y3[((size_t)b * TSZ + 127) * 400 + j];
    } else if (i < 61600) {
        int k = i - 43200; int j = (k % 1150), b = k / 1150;
        out[O + i] = cT1[j * 16 + b];
    } else if (i < 80000) {
        int k = i - 61600; int j = (k % 1150), b = k / 1150;
        out[O + i] = cT2[j * 16 + b];
    } else {
        int k = i - 80000; int j = (k % 400), b = k / 400;
        out[O + i] = cT3[j * 16 + b];
    }
}

// ---------------- launch ----------------
extern "C" void kernel_launch(void* const* d_in, const int* in_sizes, int n_in,
                              void* d_out, int out_size) {
    const float* emb  = (const float*)d_in[0];
    const float* Wih1 = (const float*)d_in[1];
    const float* Whh1 = (const float*)d_in[2];
    const float* bih1 = (const float*)d_in[3];
    const float* bhh1 = (const float*)d_in[4];
    const float* Wih2 = (const float*)d_in[5];
    const float* Whh2 = (const float*)d_in[6];
    const float* bih2 = (const float*)d_in[7];
    const float* bhh2 = (const float*)d_in[8];
    const float* Wih3 = (const float*)d_in[9];
    const float* Whh3 = (const float*)d_in[10];
    const float* bih3 = (const float*)d_in[11];
    const float* bhh3 = (const float*)d_in[12];
    const float* linb = (const float*)d_in[13];
    const int*   x    = (const int*)d_in[14];
    float* out = (float*)d_out;

    float *y0, *y1, *y2, *y3, *pre, *Wt1, *Wt2, *Wt3, *W2p, *W3p;
    float *hTa, *hTb, *cT1, *cT2, *cT3;
    unsigned* bar;
    cudaGetSymbolAddress((void**)&y0,  g_y0);
    cudaGetSymbolAddress((void**)&y1,  g_y1);
    cudaGetSymbolAddress((void**)&y2,  g_y2);
    cudaGetSymbolAddress((void**)&y3,  g_y3);
    cudaGetSymbolAddress((void**)&pre, g_pre);
    cudaGetSymbolAddress((void**)&Wt1, g_Wt1);
    cudaGetSymbolAddress((void**)&Wt2, g_Wt2);
    cudaGetSymbolAddress((void**)&Wt3, g_Wt3);
    cudaGetSymbolAddress((void**)&W2p, g_Wih2p);
    cudaGetSymbolAddress((void**)&W3p, g_Wih3p);
    cudaGetSymbolAddress((void**)&hTa, g_hTa);
    cudaGetSymbolAddress((void**)&hTb, g_hTb);
    cudaGetSymbolAddress((void**)&cT1, g_cT1);
    cudaGetSymbolAddress((void**)&cT2, g_cT2);
    cudaGetSymbolAddress((void**)&cT3, g_cT3);
    cudaGetSymbolAddress((void**)&bar, g_bar);

    const int M = TSZ * BSZ;  // 2048
    const int SMEM12 = (HSZ * 32 + 4096 + 128) * 4;  // 164096 B
    const int SMEM3  = (ESZ * 32 + 4096 + 128) * 4;  //  68096 B
    static int smem_set = 0;
    if (!smem_set) {
        cudaFuncSetAttribute(lstm_layer_k, cudaFuncAttributeMaxDynamicSharedMemorySize, SMEM12);
        smem_set = 1;
    }

    // setup — layer-1 GEMM is 4th launch (ncu -s 5 visibility window)
    embed_k<<<(TSZ * BSZ * ESZ + 255) / 256, 256>>>(emb, x, y0);
    wtrans_k<<<dim3(GP12 / 32, (HSZ + 31) / 32), dim3(32, 8)>>>(Whh1, Wt1, HSZ, GP12);
    wtrans_k<<<dim3(GP12 / 32, (HSZ + 31) / 32), dim3(32, 8)>>>(Whh2, Wt2, HSZ, GP12);
    gemm_tc<<<dim3((4 * HSZ + 127) / 128, M / 128), 256>>>(y0, Wih1, bih1, bhh1, pre,
                                                           M, 4 * HSZ, ESZ, 0);
    wtrans_k<<<dim3(GP3 / 32, (ESZ + 31) / 32), dim3(32, 8)>>>(Whh3, Wt3, ESZ, GP3);
    pad_k<<<(4 * HSZ * HPAD + 255) / 256, 256>>>(Wih2, W2p, 4 * HSZ, HSZ, HPAD);
    pad_k<<<(4 * ESZ * HPAD + 255) / 256, 256>>>(Wih3, W3p, 4 * ESZ, HSZ, HPAD);
    zero_k<<<(M * HPAD + 255) / 256, 256>>>(y1, M * HPAD);
    zero_k<<<(M * HPAD + 255) / 256, 256>>>(y2, M * HPAD);
    zero_k<<<1, 4>>>((float*)bar, 4);

    // ----- layer 1 recurrence (persistent) -----
    lstm_layer_k<<<GP12 / 32, 256, SMEM12>>>(pre, Wt1, hTa, hTb, cT1, y1,
                                             HSZ, GP12, HPAD, bar + 0);

    // ----- layer 2 -----
    gemm_tc<<<dim3((4 * HSZ + 127) / 128, M / 128), 256>>>(y1, W2p, bih2, bhh2, pre,
                                                           M, 4 * HSZ, HPAD, 0);
    lstm_layer_k<<<GP12 / 32, 256, SMEM12>>>(pre, Wt2, hTa, hTb, cT2, y2,
                                             HSZ, GP12, HPAD, bar + 1);

    // ----- layer 3 -----
    gemm_tc<<<dim3((4 * ESZ + 127) / 128, M / 128), 256>>>(y2, W3p, bih3, bhh3, pre,
                                                           M, 4 * ESZ, HPAD, 0);
    lstm_layer_k<<<GP3 / 32, 256, SMEM3>>>(pre, Wt3, hTa, hTb, cT3, y3,
                                           ESZ, GP3, ESZ, bar + 2);

    // ----- tied output projection into (B,V,T) -----
    gemm_tc<<<dim3(VSZ / 128, M / 128), 256>>>(y3, emb, linb, nullptr, out,
                                               M, VSZ, ESZ, 1);

    // ----- final states -----
    finalize_k<<<(86400 + 255) / 256, 256>>>(y1, y2, y3, cT1, cT2, cT3, out);
}